// round 2
// baseline (speedup 1.0000x reference)
#include <cuda_runtime.h>

// BiologicalNormalization: 3 chained per-row LayerNorms (D=512) with
// per-sample gathered affine params. The trailing sigmoid-gated blend
// x*g + x*(1-g) is the identity -> skipped entirely.
//
// Layout: x [B=2048, S=128, D=512] fp32. Warp-per-row, 16 floats/thread,
// all three LN passes in registers. Per-sample gamma/beta staged in smem.

#define B_DIM 2048
#define S_DIM 128
#define D_DIM 512
#define SPLIT 4                     // blocks per sample
#define ROWS_PER_BLOCK (S_DIM / SPLIT)   // 32
#define WARPS 8
#define THREADS (WARPS * 32)

__global__ __launch_bounds__(THREADS, 4)
void bionorm_kernel(const float* __restrict__ x,
                    const int* __restrict__ pathway_ids,
                    const int* __restrict__ compartment_ids,
                    const int* __restrict__ cell_type_ids,
                    const float* __restrict__ pg, const float* __restrict__ pb,
                    const float* __restrict__ cg, const float* __restrict__ cb,
                    const float* __restrict__ tg, const float* __restrict__ tb,
                    float* __restrict__ out)
{
    __shared__ __align__(16) float sp[6][D_DIM];   // g0,b0,g1,b1,g2,b2

    const int blk = blockIdx.x;
    const int b = blk / SPLIT;
    const int schunk = blk % SPLIT;

    // Stage the 6 gathered param vectors (12 KB) into shared memory.
    const int p_id = pathway_ids[b];
    const int c_id = compartment_ids[b];
    const int t_id = cell_type_ids[b];
    const float* srcs[6] = {
        pg + (size_t)p_id * D_DIM, pb + (size_t)p_id * D_DIM,
        cg + (size_t)c_id * D_DIM, cb + (size_t)c_id * D_DIM,
        tg + (size_t)t_id * D_DIM, tb + (size_t)t_id * D_DIM
    };
    const int NF4 = D_DIM / 4;                       // 128 float4 per vector
    for (int i = threadIdx.x; i < 6 * NF4; i += THREADS) {
        int which = i >> 7;          // /128
        int j = i & (NF4 - 1);
        reinterpret_cast<float4*>(sp[which])[j] =
            reinterpret_cast<const float4*>(srcs[which])[j];
    }
    __syncthreads();

    const int warp = threadIdx.x >> 5;
    const int lane = threadIdx.x & 31;
    const float inv_d = 1.0f / (float)D_DIM;
    const float eps = 1e-5f;

    // Each warp owns rows warp, warp+8, ... within this block's 32-row chunk.
    for (int r = warp; r < ROWS_PER_BLOCK; r += WARPS) {
        const int s = schunk * ROWS_PER_BLOCK + r;
        const size_t row = ((size_t)b * S_DIM + s) * D_DIM;
        const float4* __restrict__ xr = reinterpret_cast<const float4*>(x + row);

        float4 v[4];
        #pragma unroll
        for (int i = 0; i < 4; i++)
            v[i] = xr[lane + i * 32];

        #pragma unroll
        for (int p = 0; p < 3; p++) {
            // sum + sumsq in one pass
            float sum = 0.f, sq = 0.f;
            #pragma unroll
            for (int i = 0; i < 4; i++) {
                sum += v[i].x + v[i].y + v[i].z + v[i].w;
                sq  = fmaf(v[i].x, v[i].x, sq);
                sq  = fmaf(v[i].y, v[i].y, sq);
                sq  = fmaf(v[i].z, v[i].z, sq);
                sq  = fmaf(v[i].w, v[i].w, sq);
            }
            #pragma unroll
            for (int o = 16; o > 0; o >>= 1) {
                sum += __shfl_xor_sync(0xffffffffu, sum, o);
                sq  += __shfl_xor_sync(0xffffffffu, sq,  o);
            }
            const float mean = sum * inv_d;
            const float var  = fmaf(-mean, mean, sq * inv_d);
            const float rstd = rsqrtf(var + eps);

            const float4* __restrict__ gv =
                reinterpret_cast<const float4*>(sp[2 * p]);
            const float4* __restrict__ bv =
                reinterpret_cast<const float4*>(sp[2 * p + 1]);
            #pragma unroll
            for (int i = 0; i < 4; i++) {
                const float4 gg = gv[lane + i * 32];
                const float4 bb = bv[lane + i * 32];
                v[i].x = fmaf((v[i].x - mean) * rstd, gg.x, bb.x);
                v[i].y = fmaf((v[i].y - mean) * rstd, gg.y, bb.y);
                v[i].z = fmaf((v[i].z - mean) * rstd, gg.z, bb.z);
                v[i].w = fmaf((v[i].w - mean) * rstd, gg.w, bb.w);
            }
        }

        float4* __restrict__ orow = reinterpret_cast<float4*>(out + row);
        #pragma unroll
        for (int i = 0; i < 4; i++)
            orow[lane + i * 32] = v[i];
    }
}

extern "C" void kernel_launch(void* const* d_in, const int* in_sizes, int n_in,
                              void* d_out, int out_size)
{
    const float* x  = (const float*)d_in[0];
    const int* pid  = (const int*)d_in[1];
    const int* cid  = (const int*)d_in[2];
    const int* tid  = (const int*)d_in[3];
    const float* pg = (const float*)d_in[4];
    const float* pb = (const float*)d_in[5];
    const float* cg = (const float*)d_in[6];
    const float* cb = (const float*)d_in[7];
    const float* tg = (const float*)d_in[8];
    const float* tb = (const float*)d_in[9];
    // d_in[10] = W, d_in[11] = b : unused (gated blend is the identity)
    float* out = (float*)d_out;

    dim3 grid(B_DIM * SPLIT);
    dim3 block(THREADS);
    bionorm_kernel<<<grid, block>>>(x, pid, cid, tid,
                                    pg, pb, cg, cb, tg, tb, out);
}